// round 17
// baseline (speedup 1.0000x reference)
#include <cuda_runtime.h>
#include <cuda_fp16.h>
#include <math.h>

#define NROWS 32768
#define NC 1000
#define HALF_ELEMS 500            // floats per half-row
#define HALF_BYTES 2000           // bytes per half-row slot
#define DEPTH 2                   // per-warp pipeline depth
#define NWARPS 8                  // warps per CTA (4 pairs)
#define NPAIRS 4
#define GRID_ROWK 1024            // 4096 pair-engines x 8 rows = 32768
#define TOTP (GRID_ROWK * NPAIRS)
#define ROWS_PER_PAIR (NROWS / TOTP)   // 8
#define FIXSCALE 268435456.0      // 2^28

// Scratch (allocation-free device globals, zero-initialized at module load).
// Tt padded so unpredicated uint2 half-row loads stay in bounds.
__device__ __align__(16) __half g_Tth[NC * NC + 32];
__device__ unsigned long long g_sum;
__device__ unsigned int g_done;

// ---------------------------------------------------------------------------
// Kernel 1: pure transpose T -> fp16 (1024 CTAs, one 32x32 tile each).
// ---------------------------------------------------------------------------
__global__ __launch_bounds__(256) void prep_k(const float* __restrict__ T) {
    cudaTriggerProgrammaticLaunchCompletion();
    __shared__ float tile[32][33];
    const int bx = blockIdx.x & 31, by = blockIdx.x >> 5;
    const int tx = threadIdx.x & 31, ty = threadIdx.x >> 5;
    int x = bx * 32 + tx;
#pragma unroll
    for (int j = 0; j < 32; j += 8) {
        int y = by * 32 + ty + j;
        if (x < NC && y < NC)
            tile[ty + j][tx] = T[y * NC + x];
    }
    __syncthreads();
    int x2 = by * 32 + tx;
#pragma unroll
    for (int j = 0; j < 32; j += 8) {
        int y2 = bx * 32 + ty + j;
        if (x2 < NC && y2 < NC)
            g_Tth[(size_t)y2 * NC + x2] = __float2half_rn(tile[tx][ty + j]);
    }
}

// ---------------------------------------------------------------------------
// helpers
// ---------------------------------------------------------------------------
__device__ __forceinline__ unsigned int smem_u32(const void* p) {
    unsigned int a;
    asm("{ .reg .u64 t; cvta.to.shared.u64 t, %1; cvt.u32.u64 %0, t; }"
        : "=r"(a) : "l"(p));
    return a;
}
__device__ __forceinline__ void mbar_init(unsigned int mbar, unsigned int cnt) {
    asm volatile("mbarrier.init.shared.b64 [%0], %1;" :: "r"(mbar), "r"(cnt) : "memory");
}
__device__ __forceinline__ void mbar_wait(unsigned int mbar, int phase) {
    asm volatile(
        "{\n\t.reg .pred P;\n\t"
        "W_%=: mbarrier.try_wait.parity.acquire.cta.shared::cta.b64 P, [%0], %1, 0x989680;\n\t"
        "@P bra D_%=;\n\t"
        "bra W_%=;\n\t"
        "D_%=:\n\t}"
        :: "r"(mbar), "r"(phase) : "memory");
}
__device__ __forceinline__ void bulk_load(unsigned int dst, const void* src,
                                          unsigned int bytes, unsigned int mbar) {
    asm volatile("mbarrier.arrive.expect_tx.shared.b64 _, [%0], %1;"
                 :: "r"(mbar), "r"(bytes) : "memory");
    asm volatile(
        "cp.async.bulk.shared::cluster.global.mbarrier::complete_tx::bytes "
        "[%0], [%1], %2, [%3];"
        :: "r"(dst), "l"(src), "r"(bytes), "r"(mbar) : "memory");
}
__device__ __forceinline__ void pair_bar(int pair) {
    asm volatile("bar.sync %0, %1;" :: "r"(pair + 1), "r"(64) : "memory");
}

// ---------------------------------------------------------------------------
// Kernel 2 (PDL secondary): warp-PAIR row engines. 8 warps/CTA, each warp owns
// a depth-2 pipeline of 2000B half-row slots (32KB/CTA -> 6 CTAs/SM,
// 48 warps/SM). Each warp computes (Z, D, ly?) over its half; one 64-thread
// named barrier per row; even warp's lane 0 finalizes.
// ---------------------------------------------------------------------------
__global__ __launch_bounds__(256, 6) void row_k(const float* __restrict__ logits,
                                                const void* __restrict__ target,
                                                float* __restrict__ outp) {
    __shared__ __align__(128) char buf[NWARPS][DEPTH][HALF_BYTES];
    __shared__ __align__(8) unsigned long long mbars[NWARPS][DEPTH];
    __shared__ __align__(16) float4 s_partial[NWARPS];
    __shared__ unsigned long long s_pair[NPAIRS];

    const int tid  = threadIdx.x;
    const int lane = tid & 31;
    const int w    = tid >> 5;       // warp 0..7
    const int pair = w >> 1;         // 0..3
    const int h    = w & 1;          // half: 0 = cols [0,500), 1 = [500,1000)
    const int gp   = blockIdx.x * NPAIRS + pair;   // rows: gp + k*TOTP

    const unsigned int mb_base = smem_u32(&mbars[w][0]);
    const unsigned int sb_base = smem_u32(&buf[w][0][0]);

    if (tid < NWARPS * DEPTH)
        mbar_init(smem_u32(&mbars[tid / DEPTH][tid % DEPTH]), 1);
    __syncthreads();

    // Prologue: each warp's lane 0 fills its two half-row slots.
    if (lane == 0) {
#pragma unroll
        for (int s = 0; s < DEPTH; s++)
            bulk_load(sb_base + s * HALF_BYTES,
                      logits + (size_t)(gp + s * TOTP) * NC + h * HALF_ELEMS,
                      HALF_BYTES, mb_base + s * 8);
    }

    // Per-warp dtype detect on the first 8 labels (broadcast loads).
    const uint4* t4 = (const uint4*)target;
    uint4 da = t4[0], db = t4[1];
    const int is64 = ((da.y | da.w | db.y | db.w) == 0u) ? 1 : 0;

    // Label for k=0 (broadcast load).
    int ynext = is64 ? (int)((const long long*)target)[gp]
                     : ((const int*)target)[gp];
    ynext = ynext < 0 ? 0 : (ynext >= NC ? NC - 1 : ynext);

    // Gate on prep_k completion before the first g_Tth read.
    cudaGridDependencySynchronize();

    unsigned long long acc = 0ull;   // even warps only
    int s = 0, ph = 0;

    for (int k = 0; k < ROWS_PER_PAIR; k++) {
        const int row = gp + k * TOTP;
        const int y = ynext;

        // Tt half-row LDGs before the wait (unpredicated; array padded).
        const uint2* tt2 = reinterpret_cast<const uint2*>(
            g_Tth + (size_t)y * NC + h * HALF_ELEMS);
        uint2 tw[4];
#pragma unroll
        for (int j = 0; j < 4; j++) tw[j] = tt2[lane + 32 * j];

        // Prefetch next label (broadcast load, before the wait).
        if (k + 1 < ROWS_PER_PAIR) {
            int i2 = gp + (k + 1) * TOTP;
            int yy = is64 ? (int)((const long long*)target)[i2]
                          : ((const int*)target)[i2];
            ynext = yy < 0 ? 0 : (yy >= NC ? NC - 1 : yy);
        }

        const unsigned int mb   = mb_base + s * 8;
        const char*        slot = &buf[w][0][0] + s * HALF_BYTES;
        mbar_wait(mb, ph);

        // ly candidate if y falls in this warp's half (LDS broadcast).
        const int ylocal = y - h * HALF_ELEMS;
        const float lym = (ylocal >= 0 && ylocal < HALF_ELEMS)
            ? *reinterpret_cast<const float*>(slot + (size_t)ylocal * 4) : 0.f;

        // Z / D over this half (125 float4; predicated).
        const float4* r4 = reinterpret_cast<const float4*>(slot);
        float Z = 0.f, D = 0.f;
#pragma unroll
        for (int j = 0; j < 4; j++) {
            int idx = lane + 32 * j;
            if (idx < HALF_ELEMS / 4) {
                float4 v = r4[idx];
                float e0 = __expf(v.x);
                float e1 = __expf(v.y);
                float e2 = __expf(v.z);
                float e3 = __expf(v.w);
                Z += (e0 + e1) + (e2 + e3);
                float2 t01 = __half22float2(*reinterpret_cast<__half2*>(&tw[j].x));
                float2 t23 = __half22float2(*reinterpret_cast<__half2*>(&tw[j].y));
                D = fmaf(e0, t01.x, fmaf(e1, t01.y, fmaf(e2, t23.x, fmaf(e3, t23.y, D))));
            }
        }
#pragma unroll
        for (int o = 16; o > 0; o >>= 1) {
            Z += __shfl_xor_sync(0xffffffffu, Z, o);
            D += __shfl_xor_sync(0xffffffffu, D, o);
        }

        if (lane == 0) s_partial[w] = make_float4(Z, D, lym, 0.f);
        pair_bar(pair);

        if (h == 0 && lane == 0) {
            float4 a = s_partial[w];
            float4 b = s_partial[w + 1];
            float Zt = a.x + b.x;
            float Dt = a.y + b.y;
            float ly = (y < HALF_ELEMS) ? a.z : b.z;
            float lse = __logf(Zt);
            float ey  = __expf(ly);
            float val = (ey / Dt) * (lse - ly);   // beta * ce
            acc += (unsigned long long)__double2ll_rn((double)val * FIXSCALE);
        }

        // Refill own slot (safe: partner consumed before the pair barrier).
        if (lane == 0 && k + DEPTH < ROWS_PER_PAIR)
            bulk_load(sb_base + s * HALF_BYTES,
                      logits + (size_t)(row + DEPTH * TOTP) * NC + h * HALF_ELEMS,
                      HALF_BYTES, mb);

        if (++s == DEPTH) { s = 0; ph ^= 1; }
    }

    // CTA epilogue: deterministic integer reduction + self-reset of globals.
    if (h == 0 && lane == 0) s_pair[pair] = acc;
    __syncthreads();
    if (tid == 0) {
        unsigned long long tot = 0ull;
#pragma unroll
        for (int p2 = 0; p2 < NPAIRS; p2++) tot += s_pair[p2];
        atomicAdd(&g_sum, tot);
        __threadfence();
        unsigned int ticket = atomicAdd(&g_done, 1u);
        if (ticket == (unsigned)(gridDim.x - 1)) {
            unsigned long long v = atomicAdd(&g_sum, 0ull);
            outp[0] = (float)((double)v / FIXSCALE / (double)NROWS);
            g_sum = 0ull;     // reset for next graph replay
            g_done = 0u;
        }
    }
}

extern "C" void kernel_launch(void* const* d_in, const int* in_sizes, int n_in,
                              void* d_out, int out_size) {
    const float* logits = (const float*)d_in[0];   // [N, C] f32
    const float* T      = (const float*)d_in[1];   // [C, C] f32
    const void*  target = d_in[2];                 // [N] int32 or int64
    float*       out    = (float*)d_out;

    prep_k<<<1024, 256>>>(T);

    cudaLaunchConfig_t cfg = {};
    cfg.gridDim  = dim3(GRID_ROWK, 1, 1);
    cfg.blockDim = dim3(256, 1, 1);
    cfg.dynamicSmemBytes = 0;
    cfg.stream = 0;
    cudaLaunchAttribute attrs[1];
    attrs[0].id = cudaLaunchAttributeProgrammaticStreamSerialization;
    attrs[0].val.programmaticStreamSerializationAllowed = 1;
    cfg.attrs = attrs;
    cfg.numAttrs = 1;
    cudaLaunchKernelEx(&cfg, row_k, logits, target, out);
}